// round 2
// baseline (speedup 1.0000x reference)
#include <cuda_runtime.h>

#define NN 100000
#define NE 3200000
#define DF 128
#define H1 32
#define H2 16
#define NC 8

// ---- scratch (device globals; no allocs allowed) ----
__device__ __align__(16) float g_g1[NN * H1];    // g1 = (x@W1)*dinv
__device__ __align__(16) float g_agg1[NN * H1];  // scatter accumulator 1
__device__ __align__(16) float g_g2[NN * H2];    // g2 = (relu1@W2)*dinv
__device__ __align__(16) float g_agg2[NN * H2];  // scatter accumulator 2
__device__ float g_dinv[NN];
__device__ int   g_deg[NN];
__device__ __align__(8) int2 g_edge[NE];         // (src, dst) int32

// ---- K0: deg = 1 (self loop) ----
__global__ void k_init_deg() {
    int i = blockIdx.x * blockDim.x + threadIdx.x;
    if (i < NN) g_deg[i] = 1;
}

// ---- K1: pack edges -> int2, degree histogram ----
__global__ void k_edges(const int* __restrict__ ei) {
    int e = blockIdx.x * blockDim.x + threadIdx.x;
    if (e < NE) {
        int s = ei[e];
        int d = ei[NE + e];
        g_edge[e] = make_int2(s, d);
        atomicAdd(&g_deg[d], 1);
    }
}

// ---- K2: dinv = rsqrt(deg) ----
__global__ void k_dinv() {
    int i = blockIdx.x * blockDim.x + threadIdx.x;
    if (i < NN) g_dinv[i] = rsqrtf((float)g_deg[i]);
}

// ---- K3: g1 = (x @ W1) * dinv ; agg1 = g1 (self-loop term) ----
// 8 warps/block, one node per warp, W1 (128x32) staged in shared.
__global__ void k_gemm1(const float* __restrict__ x, const float* __restrict__ W1) {
    __shared__ float sW[DF * H1];      // 16 KB
    __shared__ float sx[8][DF];        // 4 KB
    int tid = threadIdx.x;
    for (int i = tid; i < DF * H1; i += 256) sW[i] = W1[i];
    __syncthreads();
    int warp = tid >> 5, lane = tid & 31;
    int node = blockIdx.x * 8 + warp;  // NN % 8 == 0, always in range
    // cooperative row load: 32 lanes x float4 = 128 floats
    float4 v = ((const float4*)(x + (size_t)node * DF))[lane];
    ((float4*)sx[warp])[lane] = v;
    __syncwarp();
    float acc = 0.f;
#pragma unroll
    for (int k = 0; k < DF; k++)
        acc = fmaf(sx[warp][k], sW[k * H1 + lane], acc);
    float g = acc * g_dinv[node];
    g_g1[node * H1 + lane]  = g;
    g_agg1[node * H1 + lane] = g;
}

// ---- K4: scatter pass 1: agg1[dst] += g1[src]  (warp per edge, 32 feats) ----
__global__ void k_scatter1() {
    long long gid = (long long)blockIdx.x * blockDim.x + threadIdx.x;
    int e = (int)(gid >> 5);
    if (e >= NE) return;
    int lane = (int)(gid & 31);
    int2 sd = g_edge[e];
    float v = g_g1[sd.x * H1 + lane];
    atomicAdd(&g_agg1[sd.y * H1 + lane], v);
}

// ---- K5: relu(dinv*agg1 + b1) @ W2 * dinv -> g2 ; agg2 = g2 ----
__global__ void k_mid(const float* __restrict__ b1, const float* __restrict__ W2) {
    __shared__ float sW[H1 * H2];      // 2 KB
    __shared__ float su[8][H1];
    int tid = threadIdx.x;
    for (int i = tid; i < H1 * H2; i += 256) sW[i] = W2[i];
    __syncthreads();
    int warp = tid >> 5, lane = tid & 31;
    int node = blockIdx.x * 8 + warp;
    float dinv = g_dinv[node];
    float u = fmaxf(fmaf(g_agg1[node * H1 + lane], dinv, b1[lane]), 0.f);
    su[warp][lane] = u;
    __syncwarp();
    if (lane < H2) {
        float acc = 0.f;
#pragma unroll
        for (int k = 0; k < H1; k++)
            acc = fmaf(su[warp][k], sW[k * H2 + lane], acc);
        float g = acc * dinv;
        g_g2[node * H2 + lane]  = g;
        g_agg2[node * H2 + lane] = g;
    }
}

// ---- K6: scatter pass 2: agg2[dst] += g2[src]  (16 lanes per edge) ----
__global__ void k_scatter2() {
    long long gid = (long long)blockIdx.x * blockDim.x + threadIdx.x;
    int e = (int)(gid >> 4);
    if (e >= NE) return;
    int lane = (int)(gid & 15);
    int2 sd = g_edge[e];
    float v = g_g2[sd.x * H2 + lane];
    atomicAdd(&g_agg2[sd.y * H2 + lane], v);
}

// ---- K7: relu(dinv*agg2 + b2) @ Wc + bc -> log_softmax -> out ----
__global__ void k_final(const float* __restrict__ b2, const float* __restrict__ Wc,
                        const float* __restrict__ bc, float* __restrict__ out) {
    int node = blockIdx.x * blockDim.x + threadIdx.x;
    if (node >= NN) return;
    float dinv = g_dinv[node];
    float u[H2];
    const float4* a = (const float4*)(g_agg2 + (size_t)node * H2);
#pragma unroll
    for (int q = 0; q < 4; q++) {
        float4 v = a[q];
        u[4 * q + 0] = v.x; u[4 * q + 1] = v.y;
        u[4 * q + 2] = v.z; u[4 * q + 3] = v.w;
    }
#pragma unroll
    for (int k = 0; k < H2; k++)
        u[k] = fmaxf(fmaf(u[k], dinv, __ldg(&b2[k])), 0.f);
    float l[NC];
#pragma unroll
    for (int j = 0; j < NC; j++) l[j] = __ldg(&bc[j]);
#pragma unroll
    for (int k = 0; k < H2; k++) {
        float uk = u[k];
#pragma unroll
        for (int j = 0; j < NC; j++)
            l[j] = fmaf(uk, __ldg(&Wc[k * NC + j]), l[j]);
    }
    float m = l[0];
#pragma unroll
    for (int j = 1; j < NC; j++) m = fmaxf(m, l[j]);
    float s = 0.f;
#pragma unroll
    for (int j = 0; j < NC; j++) s += expf(l[j] - m);
    float lse = m + logf(s);
    float4* o = (float4*)(out + (size_t)node * NC);
    o[0] = make_float4(l[0] - lse, l[1] - lse, l[2] - lse, l[3] - lse);
    o[1] = make_float4(l[4] - lse, l[5] - lse, l[6] - lse, l[7] - lse);
}

extern "C" void kernel_launch(void* const* d_in, const int* in_sizes, int n_in,
                              void* d_out, int out_size) {
    (void)out_size;
    // Map inputs by element count (all sizes distinct) — robust to ordering.
    const float* x  = nullptr; const int* ei = nullptr;
    const float* W1 = nullptr; const float* b1 = nullptr;
    const float* W2 = nullptr; const float* b2 = nullptr;
    const float* Wc = nullptr; const float* bc = nullptr;
    for (int i = 0; i < n_in; i++) {
        switch (in_sizes[i]) {
            case NN * DF:    x  = (const float*)d_in[i]; break;  // 12,800,000
            case 2 * NE:     ei = (const int*)d_in[i];   break;  //  6,400,000
            case DF * H1:    W1 = (const float*)d_in[i]; break;  //      4,096
            case H1 * H2:    W2 = (const float*)d_in[i]; break;  //        512
            case H2 * NC:    Wc = (const float*)d_in[i]; break;  //        128
            case H1:         b1 = (const float*)d_in[i]; break;  //         32
            case H2:         b2 = (const float*)d_in[i]; break;  //         16
            case NC:         bc = (const float*)d_in[i]; break;  //          8
            default: break;
        }
    }
    float* out = (float*)d_out;

    k_init_deg<<<(NN + 255) / 256, 256>>>();
    k_edges<<<(NE + 255) / 256, 256>>>(ei);
    k_dinv<<<(NN + 255) / 256, 256>>>();
    k_gemm1<<<NN / 8, 256>>>(x, W1);                 // 12500 blocks
    k_scatter1<<<(NE * 32) / 256, 256>>>();          // 400000 blocks
    k_mid<<<NN / 8, 256>>>(b1, W2);
    k_scatter2<<<(NE * 16) / 256, 256>>>();          // 200000 blocks
    k_final<<<(NN + 255) / 256, 256>>>(b2, Wc, bc, out);
}

// round 3
// speedup vs baseline: 1.0017x; 1.0017x over previous
#include <cuda_runtime.h>

#define NN 100000
#define NE 3200000
#define DF 128
#define H1 32
#define H2 16
#define NC 8

// ---- scratch (device globals; no allocs allowed) ----
__device__ __align__(16) float g_g1[NN * H1];    // g1 = (x@W1)*dinv
__device__ __align__(16) float g_agg1[NN * H1];  // scatter accumulator 1
__device__ __align__(16) float g_g2[NN * H2];    // g2 = (relu1@W2)*dinv
__device__ __align__(16) float g_agg2[NN * H2];  // scatter accumulator 2
__device__ float g_dinv[NN];
__device__ int   g_deg[NN];
__device__ __align__(8) int2 g_edge[NE];         // (src, dst) int32

// ---- K0: deg = 1 (self loop) ----
__global__ void k_init_deg() {
    int i = blockIdx.x * blockDim.x + threadIdx.x;
    if (i < NN) g_deg[i] = 1;
}

// ---- K1: pack edges -> int2, degree histogram ----
__global__ void k_edges(const int* __restrict__ ei) {
    int e = blockIdx.x * blockDim.x + threadIdx.x;
    if (e < NE) {
        int s = ei[e];
        int d = ei[NE + e];
        g_edge[e] = make_int2(s, d);
        atomicAdd(&g_deg[d], 1);
    }
}

// ---- K2: dinv = rsqrt(deg) ----
__global__ void k_dinv() {
    int i = blockIdx.x * blockDim.x + threadIdx.x;
    if (i < NN) g_dinv[i] = rsqrtf((float)g_deg[i]);
}

// ---- K3: g1 = (x @ W1) * dinv ; agg1 = g1 (self-loop term) ----
// 8 warps/block, one node per warp, W1 (128x32) staged in shared.
__global__ void k_gemm1(const float* __restrict__ x, const float* __restrict__ W1) {
    __shared__ float sW[DF * H1];      // 16 KB
    __shared__ float sx[8][DF];        // 4 KB
    int tid = threadIdx.x;
    for (int i = tid; i < DF * H1; i += 256) sW[i] = W1[i];
    __syncthreads();
    int warp = tid >> 5, lane = tid & 31;
    int node = blockIdx.x * 8 + warp;  // NN % 8 == 0, always in range
    // cooperative row load: 32 lanes x float4 = 128 floats
    float4 v = ((const float4*)(x + (size_t)node * DF))[lane];
    ((float4*)sx[warp])[lane] = v;
    __syncwarp();
    float acc = 0.f;
#pragma unroll
    for (int k = 0; k < DF; k++)
        acc = fmaf(sx[warp][k], sW[k * H1 + lane], acc);
    float g = acc * g_dinv[node];
    g_g1[node * H1 + lane]  = g;
    g_agg1[node * H1 + lane] = g;
}

// ---- K4: scatter pass 1: agg1[dst] += g1[src]  (warp per edge, 32 feats) ----
__global__ void k_scatter1() {
    long long gid = (long long)blockIdx.x * blockDim.x + threadIdx.x;
    int e = (int)(gid >> 5);
    if (e >= NE) return;
    int lane = (int)(gid & 31);
    int2 sd = g_edge[e];
    float v = g_g1[sd.x * H1 + lane];
    atomicAdd(&g_agg1[sd.y * H1 + lane], v);
}

// ---- K5: relu(dinv*agg1 + b1) @ W2 * dinv -> g2 ; agg2 = g2 ----
__global__ void k_mid(const float* __restrict__ b1, const float* __restrict__ W2) {
    __shared__ float sW[H1 * H2];      // 2 KB
    __shared__ float su[8][H1];
    int tid = threadIdx.x;
    for (int i = tid; i < H1 * H2; i += 256) sW[i] = W2[i];
    __syncthreads();
    int warp = tid >> 5, lane = tid & 31;
    int node = blockIdx.x * 8 + warp;
    float dinv = g_dinv[node];
    float u = fmaxf(fmaf(g_agg1[node * H1 + lane], dinv, b1[lane]), 0.f);
    su[warp][lane] = u;
    __syncwarp();
    if (lane < H2) {
        float acc = 0.f;
#pragma unroll
        for (int k = 0; k < H1; k++)
            acc = fmaf(su[warp][k], sW[k * H2 + lane], acc);
        float g = acc * dinv;
        g_g2[node * H2 + lane]  = g;
        g_agg2[node * H2 + lane] = g;
    }
}

// ---- K6: scatter pass 2: agg2[dst] += g2[src]  (16 lanes per edge) ----
__global__ void k_scatter2() {
    long long gid = (long long)blockIdx.x * blockDim.x + threadIdx.x;
    int e = (int)(gid >> 4);
    if (e >= NE) return;
    int lane = (int)(gid & 15);
    int2 sd = g_edge[e];
    float v = g_g2[sd.x * H2 + lane];
    atomicAdd(&g_agg2[sd.y * H2 + lane], v);
}

// ---- K7: relu(dinv*agg2 + b2) @ Wc + bc -> log_softmax -> out ----
__global__ void k_final(const float* __restrict__ b2, const float* __restrict__ Wc,
                        const float* __restrict__ bc, float* __restrict__ out) {
    int node = blockIdx.x * blockDim.x + threadIdx.x;
    if (node >= NN) return;
    float dinv = g_dinv[node];
    float u[H2];
    const float4* a = (const float4*)(g_agg2 + (size_t)node * H2);
#pragma unroll
    for (int q = 0; q < 4; q++) {
        float4 v = a[q];
        u[4 * q + 0] = v.x; u[4 * q + 1] = v.y;
        u[4 * q + 2] = v.z; u[4 * q + 3] = v.w;
    }
#pragma unroll
    for (int k = 0; k < H2; k++)
        u[k] = fmaxf(fmaf(u[k], dinv, __ldg(&b2[k])), 0.f);
    float l[NC];
#pragma unroll
    for (int j = 0; j < NC; j++) l[j] = __ldg(&bc[j]);
#pragma unroll
    for (int k = 0; k < H2; k++) {
        float uk = u[k];
#pragma unroll
        for (int j = 0; j < NC; j++)
            l[j] = fmaf(uk, __ldg(&Wc[k * NC + j]), l[j]);
    }
    float m = l[0];
#pragma unroll
    for (int j = 1; j < NC; j++) m = fmaxf(m, l[j]);
    float s = 0.f;
#pragma unroll
    for (int j = 0; j < NC; j++) s += expf(l[j] - m);
    float lse = m + logf(s);
    float4* o = (float4*)(out + (size_t)node * NC);
    o[0] = make_float4(l[0] - lse, l[1] - lse, l[2] - lse, l[3] - lse);
    o[1] = make_float4(l[4] - lse, l[5] - lse, l[6] - lse, l[7] - lse);
}

extern "C" void kernel_launch(void* const* d_in, const int* in_sizes, int n_in,
                              void* d_out, int out_size) {
    (void)out_size;
    // Map inputs by element count (all sizes distinct) — robust to ordering.
    const float* x  = nullptr; const int* ei = nullptr;
    const float* W1 = nullptr; const float* b1 = nullptr;
    const float* W2 = nullptr; const float* b2 = nullptr;
    const float* Wc = nullptr; const float* bc = nullptr;
    for (int i = 0; i < n_in; i++) {
        switch (in_sizes[i]) {
            case NN * DF:    x  = (const float*)d_in[i]; break;  // 12,800,000
            case 2 * NE:     ei = (const int*)d_in[i];   break;  //  6,400,000
            case DF * H1:    W1 = (const float*)d_in[i]; break;  //      4,096
            case H1 * H2:    W2 = (const float*)d_in[i]; break;  //        512
            case H2 * NC:    Wc = (const float*)d_in[i]; break;  //        128
            case H1:         b1 = (const float*)d_in[i]; break;  //         32
            case H2:         b2 = (const float*)d_in[i]; break;  //         16
            case NC:         bc = (const float*)d_in[i]; break;  //          8
            default: break;
        }
    }
    float* out = (float*)d_out;

    k_init_deg<<<(NN + 255) / 256, 256>>>();
    k_edges<<<(NE + 255) / 256, 256>>>(ei);
    k_dinv<<<(NN + 255) / 256, 256>>>();
    k_gemm1<<<NN / 8, 256>>>(x, W1);                 // 12500 blocks
    k_scatter1<<<(NE * 32) / 256, 256>>>();          // 400000 blocks
    k_mid<<<NN / 8, 256>>>(b1, W2);
    k_scatter2<<<(NE * 16) / 256, 256>>>();          // 200000 blocks
    k_final<<<(NN + 255) / 256, 256>>>(b2, Wc, bc, out);
}

// round 4
// speedup vs baseline: 1.0023x; 1.0005x over previous
#include <cuda_runtime.h>

#define NN 100000
#define NE 3200000
#define DF 128
#define H1 32
#define H2 16
#define NC 8

// ---- scratch (device globals; no allocs allowed) ----
__device__ __align__(16) float g_g1[NN * H1];    // g1 = (x@W1)*dinv
__device__ __align__(16) float g_agg1[NN * H1];  // scatter accumulator 1
__device__ __align__(16) float g_g2[NN * H2];    // g2 = (relu1@W2)*dinv
__device__ __align__(16) float g_agg2[NN * H2];  // scatter accumulator 2
__device__ float g_dinv[NN];
__device__ int   g_deg[NN];
__device__ __align__(8) int2 g_edge[NE];         // (src, dst) int32

// ---- K0: deg = 1 (self loop) ----
__global__ void k_init_deg() {
    int i = blockIdx.x * blockDim.x + threadIdx.x;
    if (i < NN) g_deg[i] = 1;
}

// ---- K1: pack edges -> int2, degree histogram ----
__global__ void k_edges(const int* __restrict__ ei) {
    int e = blockIdx.x * blockDim.x + threadIdx.x;
    if (e < NE) {
        int s = ei[e];
        int d = ei[NE + e];
        g_edge[e] = make_int2(s, d);
        atomicAdd(&g_deg[d], 1);
    }
}

// ---- K2: dinv = rsqrt(deg) ----
__global__ void k_dinv() {
    int i = blockIdx.x * blockDim.x + threadIdx.x;
    if (i < NN) g_dinv[i] = rsqrtf((float)g_deg[i]);
}

// ---- K3: g1 = (x @ W1) * dinv ; agg1 = g1 (self-loop term) ----
// 8 warps/block, one node per warp, W1 (128x32) staged in shared.
__global__ void k_gemm1(const float* __restrict__ x, const float* __restrict__ W1) {
    __shared__ float sW[DF * H1];      // 16 KB
    __shared__ float sx[8][DF];        // 4 KB
    int tid = threadIdx.x;
    for (int i = tid; i < DF * H1; i += 256) sW[i] = W1[i];
    __syncthreads();
    int warp = tid >> 5, lane = tid & 31;
    int node = blockIdx.x * 8 + warp;  // NN % 8 == 0, always in range
    // cooperative row load: 32 lanes x float4 = 128 floats
    float4 v = ((const float4*)(x + (size_t)node * DF))[lane];
    ((float4*)sx[warp])[lane] = v;
    __syncwarp();
    float acc = 0.f;
#pragma unroll
    for (int k = 0; k < DF; k++)
        acc = fmaf(sx[warp][k], sW[k * H1 + lane], acc);
    float g = acc * g_dinv[node];
    g_g1[node * H1 + lane]  = g;
    g_agg1[node * H1 + lane] = g;
}

// ---- K4: scatter pass 1: agg1[dst] += g1[src]  (warp per edge, 32 feats) ----
__global__ void k_scatter1() {
    long long gid = (long long)blockIdx.x * blockDim.x + threadIdx.x;
    int e = (int)(gid >> 5);
    if (e >= NE) return;
    int lane = (int)(gid & 31);
    int2 sd = g_edge[e];
    float v = g_g1[sd.x * H1 + lane];
    atomicAdd(&g_agg1[sd.y * H1 + lane], v);
}

// ---- K5: relu(dinv*agg1 + b1) @ W2 * dinv -> g2 ; agg2 = g2 ----
__global__ void k_mid(const float* __restrict__ b1, const float* __restrict__ W2) {
    __shared__ float sW[H1 * H2];      // 2 KB
    __shared__ float su[8][H1];
    int tid = threadIdx.x;
    for (int i = tid; i < H1 * H2; i += 256) sW[i] = W2[i];
    __syncthreads();
    int warp = tid >> 5, lane = tid & 31;
    int node = blockIdx.x * 8 + warp;
    float dinv = g_dinv[node];
    float u = fmaxf(fmaf(g_agg1[node * H1 + lane], dinv, b1[lane]), 0.f);
    su[warp][lane] = u;
    __syncwarp();
    if (lane < H2) {
        float acc = 0.f;
#pragma unroll
        for (int k = 0; k < H1; k++)
            acc = fmaf(su[warp][k], sW[k * H2 + lane], acc);
        float g = acc * dinv;
        g_g2[node * H2 + lane]  = g;
        g_agg2[node * H2 + lane] = g;
    }
}

// ---- K6: scatter pass 2: agg2[dst] += g2[src]  (16 lanes per edge) ----
__global__ void k_scatter2() {
    long long gid = (long long)blockIdx.x * blockDim.x + threadIdx.x;
    int e = (int)(gid >> 4);
    if (e >= NE) return;
    int lane = (int)(gid & 15);
    int2 sd = g_edge[e];
    float v = g_g2[sd.x * H2 + lane];
    atomicAdd(&g_agg2[sd.y * H2 + lane], v);
}

// ---- K7: relu(dinv*agg2 + b2) @ Wc + bc -> log_softmax -> out ----
__global__ void k_final(const float* __restrict__ b2, const float* __restrict__ Wc,
                        const float* __restrict__ bc, float* __restrict__ out) {
    int node = blockIdx.x * blockDim.x + threadIdx.x;
    if (node >= NN) return;
    float dinv = g_dinv[node];
    float u[H2];
    const float4* a = (const float4*)(g_agg2 + (size_t)node * H2);
#pragma unroll
    for (int q = 0; q < 4; q++) {
        float4 v = a[q];
        u[4 * q + 0] = v.x; u[4 * q + 1] = v.y;
        u[4 * q + 2] = v.z; u[4 * q + 3] = v.w;
    }
#pragma unroll
    for (int k = 0; k < H2; k++)
        u[k] = fmaxf(fmaf(u[k], dinv, __ldg(&b2[k])), 0.f);
    float l[NC];
#pragma unroll
    for (int j = 0; j < NC; j++) l[j] = __ldg(&bc[j]);
#pragma unroll
    for (int k = 0; k < H2; k++) {
        float uk = u[k];
#pragma unroll
        for (int j = 0; j < NC; j++)
            l[j] = fmaf(uk, __ldg(&Wc[k * NC + j]), l[j]);
    }
    float m = l[0];
#pragma unroll
    for (int j = 1; j < NC; j++) m = fmaxf(m, l[j]);
    float s = 0.f;
#pragma unroll
    for (int j = 0; j < NC; j++) s += expf(l[j] - m);
    float lse = m + logf(s);
    float4* o = (float4*)(out + (size_t)node * NC);
    o[0] = make_float4(l[0] - lse, l[1] - lse, l[2] - lse, l[3] - lse);
    o[1] = make_float4(l[4] - lse, l[5] - lse, l[6] - lse, l[7] - lse);
}

extern "C" void kernel_launch(void* const* d_in, const int* in_sizes, int n_in,
                              void* d_out, int out_size) {
    (void)out_size;
    // Map inputs by element count (all sizes distinct) — robust to ordering.
    const float* x  = nullptr; const int* ei = nullptr;
    const float* W1 = nullptr; const float* b1 = nullptr;
    const float* W2 = nullptr; const float* b2 = nullptr;
    const float* Wc = nullptr; const float* bc = nullptr;
    for (int i = 0; i < n_in; i++) {
        switch (in_sizes[i]) {
            case NN * DF:    x  = (const float*)d_in[i]; break;  // 12,800,000
            case 2 * NE:     ei = (const int*)d_in[i];   break;  //  6,400,000
            case DF * H1:    W1 = (const float*)d_in[i]; break;  //      4,096
            case H1 * H2:    W2 = (const float*)d_in[i]; break;  //        512
            case H2 * NC:    Wc = (const float*)d_in[i]; break;  //        128
            case H1:         b1 = (const float*)d_in[i]; break;  //         32
            case H2:         b2 = (const float*)d_in[i]; break;  //         16
            case NC:         bc = (const float*)d_in[i]; break;  //          8
            default: break;
        }
    }
    float* out = (float*)d_out;

    k_init_deg<<<(NN + 255) / 256, 256>>>();
    k_edges<<<(NE + 255) / 256, 256>>>(ei);
    k_dinv<<<(NN + 255) / 256, 256>>>();
    k_gemm1<<<NN / 8, 256>>>(x, W1);                 // 12500 blocks
    k_scatter1<<<(NE * 32) / 256, 256>>>();          // 400000 blocks
    k_mid<<<NN / 8, 256>>>(b1, W2);
    k_scatter2<<<(NE * 16) / 256, 256>>>();          // 200000 blocks
    k_final<<<(NN + 255) / 256, 256>>>(b2, Wc, bc, out);
}

// round 5
// speedup vs baseline: 1.0038x; 1.0015x over previous
#include <cuda_runtime.h>

#define NN 100000
#define NE 3200000
#define DF 128
#define H1 32
#define H2 16
#define NC 8

// ---- scratch (device globals; no allocs allowed) ----
__device__ __align__(16) float g_g1[NN * H1];    // g1 = (x@W1)*dinv
__device__ __align__(16) float g_agg1[NN * H1];  // scatter accumulator 1
__device__ __align__(16) float g_g2[NN * H2];    // g2 = (relu1@W2)*dinv
__device__ __align__(16) float g_agg2[NN * H2];  // scatter accumulator 2
__device__ float g_dinv[NN];
__device__ int   g_deg[NN];
__device__ __align__(8) int2 g_edge[NE];         // (src, dst) int32

// ---- K0: deg = 1 (self loop) ----
__global__ void k_init_deg() {
    int i = blockIdx.x * blockDim.x + threadIdx.x;
    if (i < NN) g_deg[i] = 1;
}

// ---- K1: pack edges -> int2, degree histogram ----
__global__ void k_edges(const int* __restrict__ ei) {
    int e = blockIdx.x * blockDim.x + threadIdx.x;
    if (e < NE) {
        int s = ei[e];
        int d = ei[NE + e];
        g_edge[e] = make_int2(s, d);
        atomicAdd(&g_deg[d], 1);
    }
}

// ---- K2: dinv = rsqrt(deg) ----
__global__ void k_dinv() {
    int i = blockIdx.x * blockDim.x + threadIdx.x;
    if (i < NN) g_dinv[i] = rsqrtf((float)g_deg[i]);
}

// ---- K3: g1 = (x @ W1) * dinv ; agg1 = g1 (self-loop term) ----
// 8 warps/block, one node per warp, W1 (128x32) staged in shared.
__global__ void k_gemm1(const float* __restrict__ x, const float* __restrict__ W1) {
    __shared__ float sW[DF * H1];      // 16 KB
    __shared__ float sx[8][DF];        // 4 KB
    int tid = threadIdx.x;
    for (int i = tid; i < DF * H1; i += 256) sW[i] = W1[i];
    __syncthreads();
    int warp = tid >> 5, lane = tid & 31;
    int node = blockIdx.x * 8 + warp;  // NN % 8 == 0, always in range
    // cooperative row load: 32 lanes x float4 = 128 floats
    float4 v = ((const float4*)(x + (size_t)node * DF))[lane];
    ((float4*)sx[warp])[lane] = v;
    __syncwarp();
    float acc = 0.f;
#pragma unroll
    for (int k = 0; k < DF; k++)
        acc = fmaf(sx[warp][k], sW[k * H1 + lane], acc);
    float g = acc * g_dinv[node];
    g_g1[node * H1 + lane]  = g;
    g_agg1[node * H1 + lane] = g;
}

// ---- K4: scatter pass 1: agg1[dst] += g1[src]  (warp per edge, 32 feats) ----
__global__ void k_scatter1() {
    long long gid = (long long)blockIdx.x * blockDim.x + threadIdx.x;
    int e = (int)(gid >> 5);
    if (e >= NE) return;
    int lane = (int)(gid & 31);
    int2 sd = g_edge[e];
    float v = g_g1[sd.x * H1 + lane];
    atomicAdd(&g_agg1[sd.y * H1 + lane], v);
}

// ---- K5: relu(dinv*agg1 + b1) @ W2 * dinv -> g2 ; agg2 = g2 ----
__global__ void k_mid(const float* __restrict__ b1, const float* __restrict__ W2) {
    __shared__ float sW[H1 * H2];      // 2 KB
    __shared__ float su[8][H1];
    int tid = threadIdx.x;
    for (int i = tid; i < H1 * H2; i += 256) sW[i] = W2[i];
    __syncthreads();
    int warp = tid >> 5, lane = tid & 31;
    int node = blockIdx.x * 8 + warp;
    float dinv = g_dinv[node];
    float u = fmaxf(fmaf(g_agg1[node * H1 + lane], dinv, b1[lane]), 0.f);
    su[warp][lane] = u;
    __syncwarp();
    if (lane < H2) {
        float acc = 0.f;
#pragma unroll
        for (int k = 0; k < H1; k++)
            acc = fmaf(su[warp][k], sW[k * H2 + lane], acc);
        float g = acc * dinv;
        g_g2[node * H2 + lane]  = g;
        g_agg2[node * H2 + lane] = g;
    }
}

// ---- K6: scatter pass 2: agg2[dst] += g2[src]  (16 lanes per edge) ----
__global__ void k_scatter2() {
    long long gid = (long long)blockIdx.x * blockDim.x + threadIdx.x;
    int e = (int)(gid >> 4);
    if (e >= NE) return;
    int lane = (int)(gid & 15);
    int2 sd = g_edge[e];
    float v = g_g2[sd.x * H2 + lane];
    atomicAdd(&g_agg2[sd.y * H2 + lane], v);
}

// ---- K7: relu(dinv*agg2 + b2) @ Wc + bc -> log_softmax -> out ----
__global__ void k_final(const float* __restrict__ b2, const float* __restrict__ Wc,
                        const float* __restrict__ bc, float* __restrict__ out) {
    int node = blockIdx.x * blockDim.x + threadIdx.x;
    if (node >= NN) return;
    float dinv = g_dinv[node];
    float u[H2];
    const float4* a = (const float4*)(g_agg2 + (size_t)node * H2);
#pragma unroll
    for (int q = 0; q < 4; q++) {
        float4 v = a[q];
        u[4 * q + 0] = v.x; u[4 * q + 1] = v.y;
        u[4 * q + 2] = v.z; u[4 * q + 3] = v.w;
    }
#pragma unroll
    for (int k = 0; k < H2; k++)
        u[k] = fmaxf(fmaf(u[k], dinv, __ldg(&b2[k])), 0.f);
    float l[NC];
#pragma unroll
    for (int j = 0; j < NC; j++) l[j] = __ldg(&bc[j]);
#pragma unroll
    for (int k = 0; k < H2; k++) {
        float uk = u[k];
#pragma unroll
        for (int j = 0; j < NC; j++)
            l[j] = fmaf(uk, __ldg(&Wc[k * NC + j]), l[j]);
    }
    float m = l[0];
#pragma unroll
    for (int j = 1; j < NC; j++) m = fmaxf(m, l[j]);
    float s = 0.f;
#pragma unroll
    for (int j = 0; j < NC; j++) s += expf(l[j] - m);
    float lse = m + logf(s);
    float4* o = (float4*)(out + (size_t)node * NC);
    o[0] = make_float4(l[0] - lse, l[1] - lse, l[2] - lse, l[3] - lse);
    o[1] = make_float4(l[4] - lse, l[5] - lse, l[6] - lse, l[7] - lse);
}

extern "C" void kernel_launch(void* const* d_in, const int* in_sizes, int n_in,
                              void* d_out, int out_size) {
    (void)out_size;
    // Map inputs by element count (all sizes distinct) — robust to ordering.
    const float* x  = nullptr; const int* ei = nullptr;
    const float* W1 = nullptr; const float* b1 = nullptr;
    const float* W2 = nullptr; const float* b2 = nullptr;
    const float* Wc = nullptr; const float* bc = nullptr;
    for (int i = 0; i < n_in; i++) {
        switch (in_sizes[i]) {
            case NN * DF:    x  = (const float*)d_in[i]; break;  // 12,800,000
            case 2 * NE:     ei = (const int*)d_in[i];   break;  //  6,400,000
            case DF * H1:    W1 = (const float*)d_in[i]; break;  //      4,096
            case H1 * H2:    W2 = (const float*)d_in[i]; break;  //        512
            case H2 * NC:    Wc = (const float*)d_in[i]; break;  //        128
            case H1:         b1 = (const float*)d_in[i]; break;  //         32
            case H2:         b2 = (const float*)d_in[i]; break;  //         16
            case NC:         bc = (const float*)d_in[i]; break;  //          8
            default: break;
        }
    }
    float* out = (float*)d_out;

    k_init_deg<<<(NN + 255) / 256, 256>>>();
    k_edges<<<(NE + 255) / 256, 256>>>(ei);
    k_dinv<<<(NN + 255) / 256, 256>>>();
    k_gemm1<<<NN / 8, 256>>>(x, W1);                 // 12500 blocks
    k_scatter1<<<(NE * 32) / 256, 256>>>();          // 400000 blocks
    k_mid<<<NN / 8, 256>>>(b1, W2);
    k_scatter2<<<(NE * 16) / 256, 256>>>();          // 200000 blocks
    k_final<<<(NN + 255) / 256, 256>>>(b2, Wc, bc, out);
}